// round 7
// baseline (speedup 1.0000x reference)
#include <cuda_runtime.h>
#include <cuda_bf16.h>

// Shapes (fixed by problem)
#define B   4
#define QN  256
#define KN  1024
#define CIN 256
#define H   128
#define VD  256
#define KTILE 128
#define QT  16          // q rows per score block

// Scratch (no cudaMalloc allowed)
__device__ float g_qp[B * QN * H];       // [row][h]
__device__ float g_kpT[B * H * KN];      // [b][h][k]  (transposed)
__device__ float g_sc[B * QN * KN];      // scores [b][q][k]

__device__ __forceinline__ float tanh_approx(float x) {
    float y;
    asm("tanh.approx.f32 %0, %1;" : "=f"(y) : "f"(x));
    return y;
}

// ---------------------------------------------------------------------------
// Merged projection. Blocks [0, 64): queries -> g_qp.  Blocks [64, 320): keys
// -> g_kpT ([b][h][k]).  16 rows x 128 h per block, 256 threads.
// ---------------------------------------------------------------------------
#define QBLOCKS ((B * QN) / 16)   // 64
#define KBLOCKS ((B * KN) / 16)   // 256

__global__ __launch_bounds__(256) void proj_kernel(
        const float* __restrict__ queries, const float* __restrict__ keys,
        const float* __restrict__ W_q,     const float* __restrict__ W_k) {
    __shared__ float Wt[32][130];   // [cc][h]
    __shared__ float ins[16][33];   // [r][cc]

    const int tid = threadIdx.x;
    const bool is_q = (blockIdx.x < QBLOCKS);
    const float* in = is_q ? queries : keys;
    const float* W  = is_q ? W_q : W_k;
    const int rowbase = (is_q ? blockIdx.x : blockIdx.x - QBLOCKS) * 16;

    const int h0 = 2 * (tid & 63);
    const int rg = tid >> 6;

    float acc[4][2];
#pragma unroll
    for (int i = 0; i < 4; i++) { acc[i][0] = 0.f; acc[i][1] = 0.f; }

    for (int cb = 0; cb < CIN; cb += 32) {
        __syncthreads();
#pragma unroll
        for (int i = 0; i < 16; i++) {
            int idx = i * 256 + tid;
            int h = idx >> 5, cc = idx & 31;
            Wt[cc][h] = W[h * CIN + cb + cc];
        }
        {
            int idx = tid;
            int r = idx >> 5, cc = idx & 31;
            ins[r][cc] = in[(rowbase + r) * CIN + cb + cc];
            idx = 256 + tid;
            r = idx >> 5; cc = idx & 31;
            ins[r][cc] = in[(rowbase + r) * CIN + cb + cc];
        }
        __syncthreads();
#pragma unroll
        for (int cc = 0; cc < 32; cc++) {
            float2 w = *(const float2*)&Wt[cc][h0];
#pragma unroll
            for (int i = 0; i < 4; i++) {
                float x = ins[rg * 4 + i][cc];
                acc[i][0] += x * w.x;
                acc[i][1] += x * w.y;
            }
        }
    }

    if (is_q) {
#pragma unroll
        for (int i = 0; i < 4; i++) {
            int r = rowbase + rg * 4 + i;
            *(float2*)&g_qp[r * H + h0] = make_float2(acc[i][0], acc[i][1]);
        }
    } else {
#pragma unroll
        for (int i = 0; i < 4; i++) {
            int r = rowbase + rg * 4 + i;
            int b = r >> 10;
            int k = r & 1023;
            g_kpT[(b * H + h0)     * KN + k] = acc[i][0];
            g_kpT[(b * H + h0 + 1) * KN + k] = acc[i][1];
        }
    }
}

// ---------------------------------------------------------------------------
// Score kernel: one 16q x 128k tile per block.
// Grid (KN/KTILE=8, QN/QT=16, B). 256 threads; thread = 4q x 2k.
// Per h: k float2 (8B) feeds 8 tanh; q float4 broadcast; w broadcast.
// Blocks with kb >= valid exit immediately (kernel B never reads those k).
// ---------------------------------------------------------------------------
#define SM_KS  (H * KTILE)   // 16384 floats
#define SM_QT  (H * QT)      // 2048 floats, [h][q]
#define SM_WV  (H)
#define SCORE_SMEM_FLOATS (SM_KS + SM_QT + SM_WV)

__global__ __launch_bounds__(256) void score_kernel(
        const int*   __restrict__ valid_lens,
        const float* __restrict__ w_v) {
    extern __shared__ float sm[];
    float* ks  = sm;             // [h][KTILE]
    float* qsT = sm + SM_KS;     // [h][QT]
    float* wvs = qsT + SM_QT;    // [h]

    const int kb = blockIdx.x * KTILE;
    const int qt = blockIdx.y;
    const int b  = blockIdx.z;
    const int valid = valid_lens[b];
    if (kb >= valid) return;

    const int tid  = threadIdx.x;
    const int rowq = b * QN + qt * QT;

    // Stage q tile transposed [h][QT]
    for (int i = tid; i < (QT * H) / 4; i += 256) {   // 512 float4s
        int q  = i >> 5;            // 32 float4 per q row
        int hx = i & 31;
        float4 v = *(const float4*)&g_qp[(rowq + q) * H + hx * 4];
        qsT[(hx * 4 + 0) * QT + q] = v.x;
        qsT[(hx * 4 + 1) * QT + q] = v.y;
        qsT[(hx * 4 + 2) * QT + q] = v.z;
        qsT[(hx * 4 + 3) * QT + q] = v.w;
    }
    if (tid < H) wvs[tid] = w_v[tid];

    // Stage k tile [h][KTILE] (contiguous float4 from pre-transposed g_kpT)
    {
        const float* kbase = g_kpT + b * H * KN + kb;
#pragma unroll
        for (int j = 0; j < 16; j++) {
            int i = j * 256 + tid;           // 4096 float4s
            int h = i >> 5, kx = i & 31;
            ((float4*)ks)[h * 32 + kx] = *(const float4*)(kbase + h * KN + kx * 4);
        }
    }
    __syncthreads();

    const int qg  = tid >> 6;          // q group: rows qg*4 .. qg*4+3
    const int kk0 = 2 * (tid & 63);    // k pair

    float a[4][2];
#pragma unroll
    for (int i = 0; i < 4; i++) { a[i][0] = 0.f; a[i][1] = 0.f; }

#pragma unroll 8
    for (int h = 0; h < H; h++) {
        float4 qv = *(const float4*)&qsT[h * QT + qg * 4];   // broadcast
        float  w  = wvs[h];                                  // broadcast
        float2 kv = *(const float2*)&ks[h * KTILE + kk0];
        a[0][0] += w * tanh_approx(qv.x + kv.x);
        a[0][1] += w * tanh_approx(qv.x + kv.y);
        a[1][0] += w * tanh_approx(qv.y + kv.x);
        a[1][1] += w * tanh_approx(qv.y + kv.y);
        a[2][0] += w * tanh_approx(qv.z + kv.x);
        a[2][1] += w * tanh_approx(qv.z + kv.y);
        a[3][0] += w * tanh_approx(qv.w + kv.x);
        a[3][1] += w * tanh_approx(qv.w + kv.y);
    }

#pragma unroll
    for (int i = 0; i < 4; i++) {
        *(float2*)&g_sc[(rowq + qg * 4 + i) * KN + kb + kk0] =
            make_float2(a[i][0], a[i][1]);
    }
}

// ---------------------------------------------------------------------------
// Softmax + AV. Grid = B*QN/8 = 128 blocks, 256 threads. Block = 8 q rows.
// Scores staged in smem (32KB); softmax 1 warp/row; AV thread owns v=tid,
// probs read as broadcast LDS.128, V loads 16-deep for MLP.
// ---------------------------------------------------------------------------
__global__ __launch_bounds__(256) void smax_av_kernel(
        const float* __restrict__ values,
        const int*   __restrict__ valid_lens,
        float*       __restrict__ out) {
    __shared__ float srow[8 * KN];     // 32KB

    const int tid = threadIdx.x;
    const int b   = blockIdx.x >> 5;   // QN/8 = 32 blocks per batch
    const int qt  = blockIdx.x & 31;
    const int rowq = b * QN + qt * 8;
    const int valid = valid_lens[b];

    // Stage 8 score rows (contiguous region of g_sc)
    {
        const float4* src = (const float4*)(g_sc + rowq * KN);
        float4* dst = (float4*)srow;
#pragma unroll
        for (int j = 0; j < 8; j++) dst[j * 256 + tid] = src[j * 256 + tid];
    }
    __syncthreads();

    // Masked softmax: warp w owns row w
    {
        const int w = tid >> 5, lane = tid & 31;
        float* row = srow + w * KN;
        float m = -1e30f;
        for (int k = lane; k < valid; k += 32) m = fmaxf(m, row[k]);
#pragma unroll
        for (int off = 16; off; off >>= 1)
            m = fmaxf(m, __shfl_xor_sync(0xffffffffu, m, off));
        float s = 0.f;
        for (int k = lane; k < valid; k += 32) {
            float e = __expf(row[k] - m);
            row[k] = e;
            s += e;
        }
#pragma unroll
        for (int off = 16; off; off >>= 1)
            s += __shfl_xor_sync(0xffffffffu, s, off);
        float inv = 1.0f / s;
        for (int k = lane; k < valid; k += 32) row[k] *= inv;
    }
    __syncthreads();

    // AV: thread owns column v = tid; 8 q accumulators.
    float o[8];
#pragma unroll
    for (int q = 0; q < 8; q++) o[q] = 0.f;
    const float* Vb = values + b * KN * VD + tid;

    int k = 0;
    for (; k + 16 <= valid; k += 16) {
        float v[16];
#pragma unroll
        for (int kk = 0; kk < 16; kk++) v[kk] = Vb[(k + kk) * VD];
#pragma unroll
        for (int kk = 0; kk < 16; kk += 4) {
#pragma unroll
            for (int q = 0; q < 8; q++) {
                float4 p = *(const float4*)&srow[q * KN + k + kk];
                o[q] += p.x * v[kk] + p.y * v[kk + 1]
                      + p.z * v[kk + 2] + p.w * v[kk + 3];
            }
        }
    }
    for (; k < valid; k++) {
        float v = Vb[k * VD];
#pragma unroll
        for (int q = 0; q < 8; q++) o[q] += srow[q * KN + k] * v;
    }

#pragma unroll
    for (int q = 0; q < 8; q++) out[(rowq + q) * VD + tid] = o[q];
}

extern "C" void kernel_launch(void* const* d_in, const int* in_sizes, int n_in,
                              void* d_out, int out_size) {
    const float* queries    = (const float*)d_in[0];   // [B,QN,CIN]
    const float* keys       = (const float*)d_in[1];   // [B,KN,CIN]
    const float* values     = (const float*)d_in[2];   // [B,KN,VD]
    const int*   valid_lens = (const int*)  d_in[3];   // [B]
    const float* W_q        = (const float*)d_in[4];   // [H,CIN]
    const float* W_k        = (const float*)d_in[5];   // [H,CIN]
    const float* w_v        = (const float*)d_in[6];   // [H]
    float* out = (float*)d_out;                        // [B,QN,VD]

    (void)in_sizes; (void)n_in; (void)out_size;

    proj_kernel<<<QBLOCKS + KBLOCKS, 256>>>(queries, keys, W_q, W_k);

    const int score_smem = SCORE_SMEM_FLOATS * (int)sizeof(float);  // 74240 B
    cudaFuncSetAttribute(score_kernel,
                         cudaFuncAttributeMaxDynamicSharedMemorySize, score_smem);
    score_kernel<<<dim3(KN / KTILE, QN / QT, B), 256, score_smem>>>(valid_lens, w_v);

    smax_av_kernel<<<B * (QN / 8), 256>>>(values, valid_lens, out);
}

// round 9
// speedup vs baseline: 1.1225x; 1.1225x over previous
#include <cuda_runtime.h>
#include <cuda_bf16.h>

// Shapes (fixed by problem)
#define B   4
#define QN  256
#define KN  1024
#define CIN 256
#define H   128
#define VD  256
#define QT  16      // q rows per score block
#define KT2 64      // k cols per score block

// Scratch (no cudaMalloc allowed)
__device__ float g_qp[B * QN * H];       // [row][h]
__device__ float g_kpT[B * H * KN];      // [b][h][k]  (transposed)
__device__ float g_sc[B * QN * KN];      // scores [b][q][k]

__device__ __forceinline__ float tanh_approx(float x) {
    float y;
    asm("tanh.approx.f32 %0, %1;" : "=f"(y) : "f"(x));
    return y;
}

// ---------------------------------------------------------------------------
// Projection GEMM. Block = 32 rows x 64 h. grid = (160, 2):
//   grid.x < 32  -> queries (1024 rows) -> g_qp
//   grid.x >= 32 -> keys (4096 rows)    -> g_kpT (transposed [b][h][k])
// 256 threads, thread = 4 rows x 2 h. Inner iter: 1 LDS128 + 1 LDS64 + 8 FMA.
// ---------------------------------------------------------------------------
#define PR_ROWS 32
#define PR_H    64
#define QROWBLKS ((B * QN) / PR_ROWS)    // 32

__global__ __launch_bounds__(256) void proj_kernel(
        const float* __restrict__ queries, const float* __restrict__ keys,
        const float* __restrict__ W_q,     const float* __restrict__ W_k) {
    __shared__ float Wt[32][66];    // [cc][h]  pad 66 (even, conflict-light)
    __shared__ float ins[32][36];   // [cc][r]  pad 36 (16B-aligned float4 rows)

    const int tid = threadIdx.x;
    const int rowblk = blockIdx.x;
    const int hbase  = blockIdx.y * PR_H;
    const bool is_q = (rowblk < QROWBLKS);
    const float* in = is_q ? queries : keys;
    const float* W  = is_q ? W_q : W_k;
    const int rowbase = (is_q ? rowblk : rowblk - QROWBLKS) * PR_ROWS;

    const int r0 = (tid & 7) * 4;    // rows r0..r0+3
    const int h0 = (tid >> 3) * 2;   // h pair (0..62)

    float acc[4][2];
#pragma unroll
    for (int i = 0; i < 4; i++) { acc[i][0] = 0.f; acc[i][1] = 0.f; }

    for (int cb = 0; cb < CIN; cb += 32) {
        __syncthreads();
        // Stage W chunk: 64 h x 32 cc (coalesced LDG, transposed store)
#pragma unroll
        for (int i = 0; i < 8; i++) {
            int idx = i * 256 + tid;
            int h = idx >> 5, cc = idx & 31;
            Wt[cc][h] = W[(hbase + h) * CIN + cb + cc];
        }
        // Stage input chunk: 32 rows x 32 cc (coalesced LDG, transposed store)
#pragma unroll
        for (int i = 0; i < 4; i++) {
            int idx = i * 256 + tid;
            int r = idx >> 5, cc = idx & 31;
            ins[cc][r] = in[(rowbase + r) * CIN + cb + cc];
        }
        __syncthreads();
#pragma unroll
        for (int cc = 0; cc < 32; cc++) {
            float2 w = *(const float2*)&Wt[cc][h0];
            float4 x = *(const float4*)&ins[cc][r0];
            acc[0][0] += x.x * w.x;  acc[0][1] += x.x * w.y;
            acc[1][0] += x.y * w.x;  acc[1][1] += x.y * w.y;
            acc[2][0] += x.z * w.x;  acc[2][1] += x.z * w.y;
            acc[3][0] += x.w * w.x;  acc[3][1] += x.w * w.y;
        }
    }

    if (is_q) {
#pragma unroll
        for (int i = 0; i < 4; i++) {
            int r = rowbase + r0 + i;
            *(float2*)&g_qp[r * H + hbase + h0] = make_float2(acc[i][0], acc[i][1]);
        }
    } else {
        int rk = rowbase + r0;         // global key row; whole block same batch
        int b = rk >> 10;
        int k = rk & 1023;             // multiple of 4 -> aligned float4
        float4 v0 = make_float4(acc[0][0], acc[1][0], acc[2][0], acc[3][0]);
        float4 v1 = make_float4(acc[0][1], acc[1][1], acc[2][1], acc[3][1]);
        *(float4*)&g_kpT[(b * H + hbase + h0)     * KN + k] = v0;
        *(float4*)&g_kpT[(b * H + hbase + h0 + 1) * KN + k] = v1;
    }
}

// ---------------------------------------------------------------------------
// Score kernel: one 16q x 64k tile per block. grid (KN/64=16, QN/16=16, B).
// 256 threads; thread = 2q x 2k. Per h: 1 LDS64(k) + 3 uniform LDS + 4 tanh.
// 41.5KB smem -> 5 resident blocks/SM. Masked tiles exit immediately.
// ---------------------------------------------------------------------------
#define SM_KS  (H * KT2)     // 8192 floats
#define SM_QS  (QT * H)      // 2048 floats [q][h]
#define SCORE_SMEM_FLOATS (SM_KS + SM_QS + H)

__global__ __launch_bounds__(256) void score_kernel(
        const int*   __restrict__ valid_lens,
        const float* __restrict__ w_v) {
    extern __shared__ float sm[];
    float* ks  = sm;             // [h][KT2]
    float* qs  = sm + SM_KS;     // [q][h]
    float* wvs = qs + SM_QS;     // [h]

    const int kb = blockIdx.x * KT2;
    const int b  = blockIdx.z;
    const int valid = valid_lens[b];
    if (kb >= valid) return;

    const int tid  = threadIdx.x;
    const int rowq = b * QN + blockIdx.y * QT;

    // Stage q tile [q][h] (plain contiguous copy) + w_v
    {
        const float4* src = (const float4*)(g_qp + rowq * H);
        float4* dst = (float4*)qs;
        dst[tid]       = src[tid];
        dst[tid + 256] = src[tid + 256];
    }
    if (tid < H) wvs[tid] = w_v[tid];

    // Stage k tile [h][KT2] from pre-transposed g_kpT (contiguous float4)
    {
        const float* kbase = g_kpT + b * H * KN + kb;
#pragma unroll
        for (int j = 0; j < 8; j++) {
            int i = j * 256 + tid;         // 2048 float4s
            int h = i >> 4, kx = i & 15;
            ((float4*)ks)[h * 16 + kx] = *(const float4*)(kbase + h * KN + kx * 4);
        }
    }
    __syncthreads();

    const int qg  = tid >> 5;          // warp-uniform q pair (0..7)
    const int kk0 = 2 * (tid & 31);    // k pair (0..62)
    const float* q0p = qs + (qg * 2) * H;
    const float* q1p = q0p + H;

    float a00 = 0.f, a01 = 0.f, a10 = 0.f, a11 = 0.f;
#pragma unroll 8
    for (int h = 0; h < H; h++) {
        float2 kv = *(const float2*)&ks[h * KT2 + kk0];
        float  w  = wvs[h];                // uniform
        float  q0 = q0p[h];                // uniform
        float  q1 = q1p[h];                // uniform
        a00 += w * tanh_approx(q0 + kv.x);
        a01 += w * tanh_approx(q0 + kv.y);
        a10 += w * tanh_approx(q1 + kv.x);
        a11 += w * tanh_approx(q1 + kv.y);
    }

    *(float2*)&g_sc[(rowq + qg * 2)     * KN + kb + kk0] = make_float2(a00, a01);
    *(float2*)&g_sc[(rowq + qg * 2 + 1) * KN + kb + kk0] = make_float2(a10, a11);
}

// ---------------------------------------------------------------------------
// Softmax + AV. Grid = B*QN/8 = 128 blocks, 256 threads. Block = 8 q rows.
// ---------------------------------------------------------------------------
__global__ __launch_bounds__(256) void smax_av_kernel(
        const float* __restrict__ values,
        const int*   __restrict__ valid_lens,
        float*       __restrict__ out) {
    __shared__ float srow[8 * KN];     // 32KB

    const int tid = threadIdx.x;
    const int b   = blockIdx.x >> 5;
    const int qt  = blockIdx.x & 31;
    const int rowq = b * QN + qt * 8;
    const int valid = valid_lens[b];

    // Stage 8 score rows
    {
        const float4* src = (const float4*)(g_sc + rowq * KN);
        float4* dst = (float4*)srow;
#pragma unroll
        for (int j = 0; j < 8; j++) dst[j * 256 + tid] = src[j * 256 + tid];
    }
    __syncthreads();

    // Masked softmax: warp w owns row w
    {
        const int w = tid >> 5, lane = tid & 31;
        float* row = srow + w * KN;
        float m = -1e30f;
        for (int k = lane; k < valid; k += 32) m = fmaxf(m, row[k]);
#pragma unroll
        for (int off = 16; off; off >>= 1)
            m = fmaxf(m, __shfl_xor_sync(0xffffffffu, m, off));
        float s = 0.f;
        for (int k = lane; k < valid; k += 32) {
            float e = __expf(row[k] - m);
            row[k] = e;
            s += e;
        }
#pragma unroll
        for (int off = 16; off; off >>= 1)
            s += __shfl_xor_sync(0xffffffffu, s, off);
        float inv = 1.0f / s;
        for (int k = lane; k < valid; k += 32) row[k] *= inv;
    }
    __syncthreads();

    // AV: thread owns column v = tid; 8 q accumulators; MLP-16 V loads.
    float o[8];
#pragma unroll
    for (int q = 0; q < 8; q++) o[q] = 0.f;
    const float* Vb = values + b * KN * VD + tid;

    int k = 0;
    for (; k + 16 <= valid; k += 16) {
        float v[16];
#pragma unroll
        for (int kk = 0; kk < 16; kk++) v[kk] = Vb[(k + kk) * VD];
#pragma unroll
        for (int kk = 0; kk < 16; kk += 4) {
#pragma unroll
            for (int q = 0; q < 8; q++) {
                float4 p = *(const float4*)&srow[q * KN + k + kk];
                o[q] += p.x * v[kk] + p.y * v[kk + 1]
                      + p.z * v[kk + 2] + p.w * v[kk + 3];
            }
        }
    }
    for (; k < valid; k++) {
        float v = Vb[k * VD];
#pragma unroll
        for (int q = 0; q < 8; q++) o[q] += srow[q * KN + k] * v;
    }

#pragma unroll
    for (int q = 0; q < 8; q++) out[(rowq + q) * VD + tid] = o[q];
}

extern "C" void kernel_launch(void* const* d_in, const int* in_sizes, int n_in,
                              void* d_out, int out_size) {
    const float* queries    = (const float*)d_in[0];   // [B,QN,CIN]
    const float* keys       = (const float*)d_in[1];   // [B,KN,CIN]
    const float* values     = (const float*)d_in[2];   // [B,KN,VD]
    const int*   valid_lens = (const int*)  d_in[3];   // [B]
    const float* W_q        = (const float*)d_in[4];   // [H,CIN]
    const float* W_k        = (const float*)d_in[5];   // [H,CIN]
    const float* w_v        = (const float*)d_in[6];   // [H]
    float* out = (float*)d_out;                        // [B,QN,VD]

    (void)in_sizes; (void)n_in; (void)out_size;

    proj_kernel<<<dim3(QROWBLKS + (B * KN) / PR_ROWS, 2), 256>>>(
        queries, keys, W_q, W_k);

    const int score_smem = SCORE_SMEM_FLOATS * (int)sizeof(float);  // ~41.5KB
    score_kernel<<<dim3(KN / KT2, QN / QT, B), 256, score_smem>>>(valid_lens, w_v);

    smax_av_kernel<<<B * (QN / 8), 256>>>(values, valid_lens, out);
}